// round 1
// baseline (speedup 1.0000x reference)
#include <cuda_runtime.h>
#include <math.h>

#define BQ    8
#define TSZ   288
#define NSZ   2000
#define FLSZ  145
#define ESZ   128
#define IDSZ  16
#define DSZ   144      // E + ID
#define HSZ   128
#define KTOP  20
#define NHB   (NSZ*HSZ)

// ---------------- scratch (__device__ globals: allocation-free) ----------------
__device__ float g_cos[FLSZ*TSZ];
__device__ float g_sin[FLSZ*TSZ];
__device__ float g_xf  [BQ*FLSZ*NSZ];   // |rfft|, [b][f][n]
__device__ float g_invn[BQ*FLSZ];
__device__ float g_invf[BQ*NSZ];
__device__ float g_xe  [BQ*NSZ*ESZ];    // [b][n][e]
__device__ float g_x1  [BQ*NSZ*HSZ];    // [b][n][h]  (post-ReLU)
__device__ float g_mu  [BQ];
__device__ float g_rstd[BQ];
__device__ float g_wcs [HSZ];           // column sums of Wxabs
__device__ float g_adp [BQ*NSZ*HSZ];    // [b][n][k]
__device__ float g_adj [BQ*NSZ*NSZ];    // relu(adj), [b][n][m] (128 MB)

// ---------------- 1. DFT basis (exact integer phase reduction) ----------------
__global__ void k_basis() {
    int i = blockIdx.x * blockDim.x + threadIdx.x;
    if (i < FLSZ * TSZ) {
        int f = i / TSZ, t = i % TSZ;
        int m = (f * t) % TSZ;                       // exact
        float ang = (float)((double)m * 6.283185307179586 / (double)TSZ);
        g_cos[i] = cosf(ang);
        g_sin[i] = sinf(ang);
    }
}

// ---------------- 2. |rfft| as tiled GEMM: [32f x 128n] tiles ----------------
__global__ void k_dft(const float* __restrict__ x) {
    __shared__ float xs[16][128];
    __shared__ float cs[16][32];
    __shared__ float ss[16][32];
    int b  = blockIdx.z;
    int n0 = blockIdx.x * 128;
    int f0 = blockIdx.y * 32;
    int tid = threadIdx.x;
    int tf = tid >> 5;          // 0..7  -> 4 freqs each
    int tn = tid & 31;          // 0..31 -> 4 nodes each

    float accre[4][4] = {};
    float accim[4][4] = {};

    for (int t0 = 0; t0 < TSZ; t0 += 16) {
        for (int idx = tid; idx < 2048; idx += 256) {
            int tt = idx >> 7, n = idx & 127;
            int gn = n0 + n;
            xs[tt][n] = (gn < NSZ) ? x[(b * TSZ + t0 + tt) * NSZ + gn] : 0.f;
        }
        for (int idx = tid; idx < 512; idx += 256) {
            int tt = idx & 15, f = idx >> 4;
            int gf = f0 + f;
            float c = 0.f, s = 0.f;
            if (gf < FLSZ) { c = g_cos[gf * TSZ + t0 + tt]; s = g_sin[gf * TSZ + t0 + tt]; }
            cs[tt][f] = c; ss[tt][f] = s;
        }
        __syncthreads();
        #pragma unroll
        for (int tt = 0; tt < 16; ++tt) {
            float xv[4], cv[4], sv[4];
            *(float4*)xv = *(const float4*)&xs[tt][tn * 4];
            *(float4*)cv = *(const float4*)&cs[tt][tf * 4];
            *(float4*)sv = *(const float4*)&ss[tt][tf * 4];
            #pragma unroll
            for (int i = 0; i < 4; ++i)
                #pragma unroll
                for (int j = 0; j < 4; ++j) {
                    accre[i][j] += cv[i] * xv[j];
                    accim[i][j] += sv[i] * xv[j];
                }
        }
        __syncthreads();
    }
    #pragma unroll
    for (int i = 0; i < 4; ++i) {
        int f = f0 + tf * 4 + i;
        if (f >= FLSZ) continue;
        #pragma unroll
        for (int j = 0; j < 4; ++j) {
            int n = n0 + tn * 4 + j;
            if (n >= NSZ) continue;
            float re = accre[i][j], im = accim[i][j];
            g_xf[(b * FLSZ + f) * NSZ + n] = sqrtf(re * re + im * im);
        }
    }
}

// ---------------- 3. norm over nodes (axis=1) ----------------
__global__ void k_invn() {
    int f = blockIdx.x, b = blockIdx.y;
    const float* p = &g_xf[(b * FLSZ + f) * NSZ];
    float s = 0.f;
    for (int i = threadIdx.x; i < NSZ; i += 256) { float v = p[i]; s += v * v; }
    __shared__ float red[256];
    red[threadIdx.x] = s; __syncthreads();
    for (int st = 128; st > 0; st >>= 1) {
        if (threadIdx.x < st) red[threadIdx.x] += red[threadIdx.x + st];
        __syncthreads();
    }
    if (threadIdx.x == 0)
        g_invn[b * FLSZ + f] = 1.f / fmaxf(sqrtf(red[0]), 1e-12f);
}

// ---------------- 4. norm over freq (axis=2), after node-norm ----------------
__global__ void k_invf() {
    int n = blockIdx.x * 256 + threadIdx.x;
    int b = blockIdx.y;
    if (n >= NSZ) return;
    float s = 0.f;
    for (int f = 0; f < FLSZ; ++f) {
        float v = g_xf[(b * FLSZ + f) * NSZ + n] * g_invn[b * FLSZ + f];
        s += v * v;
    }
    g_invf[b * NSZ + n] = 1.f / fmaxf(sqrtf(s), 1e-12f);
}

// ---------------- 5. xe = normalized(xf) @ Ex  (TN GEMM, scales fused) --------
__global__ void k_xe(const float* __restrict__ Ex) {
    __shared__ float As[16][128];
    __shared__ float Bs[16][128];
    int b = blockIdx.z, n0 = blockIdx.x * 128;
    int tid = threadIdx.x, tx = tid & 15, ty = tid >> 4;
    float acc[8][8] = {};
    for (int f0 = 0; f0 < 160; f0 += 16) {
        for (int idx = tid; idx < 2048; idx += 256) {
            int r = idx >> 7, c = idx & 127;
            int f = f0 + r, n = n0 + c;
            As[r][c] = (f < FLSZ && n < NSZ)
                       ? g_xf[(b * FLSZ + f) * NSZ + n] * g_invn[b * FLSZ + f] : 0.f;
            Bs[r][c] = (f < FLSZ) ? Ex[f * ESZ + c] : 0.f;
        }
        __syncthreads();
        #pragma unroll
        for (int kk = 0; kk < 16; ++kk) {
            float a[8], bv[8];
            *(float4*)&a[0]  = *(const float4*)&As[kk][ty * 8];
            *(float4*)&a[4]  = *(const float4*)&As[kk][ty * 8 + 4];
            *(float4*)&bv[0] = *(const float4*)&Bs[kk][tx * 8];
            *(float4*)&bv[4] = *(const float4*)&Bs[kk][tx * 8 + 4];
            #pragma unroll
            for (int i = 0; i < 8; ++i)
                #pragma unroll
                for (int j = 0; j < 8; ++j) acc[i][j] += a[i] * bv[j];
        }
        __syncthreads();
    }
    #pragma unroll
    for (int i = 0; i < 8; ++i) {
        int n = n0 + ty * 8 + i;
        if (n >= NSZ) continue;
        float sc = g_invf[b * NSZ + n];
        #pragma unroll
        for (int j = 0; j < 8; ++j)
            g_xe[(b * NSZ + n) * ESZ + tx * 8 + j] = acc[i][j] * sc;
    }
}

// ---------------- 6. x1 = relu(per-node [8,144]@[144,128]) ----------------
__global__ void k_x1(const float* __restrict__ nodes, const float* __restrict__ Wd) {
    __shared__ float xk[BQ][DSZ];
    int n = blockIdx.x;
    int h = threadIdx.x;   // 128 threads
    for (int idx = h; idx < BQ * ESZ; idx += 128) {
        int bb = idx >> 7, e = idx & 127;
        xk[bb][e] = g_xe[(bb * NSZ + n) * ESZ + e];
    }
    for (int idx = h; idx < BQ * IDSZ; idx += 128) {
        int bb = idx >> 4, i2 = idx & 15;
        xk[bb][ESZ + i2] = nodes[n * IDSZ + i2];
    }
    __syncthreads();
    float acc[BQ] = {};
    const float* wp = &Wd[(size_t)n * DSZ * HSZ + h];
    #pragma unroll 4
    for (int d = 0; d < DSZ; ++d) {
        float w = wp[d * HSZ];
        #pragma unroll
        for (int bb = 0; bb < BQ; ++bb) acc[bb] += xk[bb][d] * w;
    }
    #pragma unroll
    for (int bb = 0; bb < BQ; ++bb)
        g_x1[(bb * NSZ + n) * HSZ + h] = fmaxf(acc[bb], 0.f);
}

// ---------------- 7. LN stats over (N,H) per batch ----------------
__global__ void k_ln() {
    int b = blockIdx.x;
    const float* p = &g_x1[b * NHB];
    double s = 0.0, q = 0.0;
    for (int i = threadIdx.x; i < NHB; i += 512) {
        float v = p[i]; s += v; q += (double)v * v;
    }
    __shared__ double rs[512], rq[512];
    rs[threadIdx.x] = s; rq[threadIdx.x] = q; __syncthreads();
    for (int st = 256; st > 0; st >>= 1) {
        if (threadIdx.x < st) { rs[threadIdx.x] += rs[threadIdx.x + st]; rq[threadIdx.x] += rq[threadIdx.x + st]; }
        __syncthreads();
    }
    if (threadIdx.x == 0) {
        double mu  = rs[0] / (double)NHB;
        double var = rq[0] / (double)NHB - mu * mu;
        g_mu[b]   = (float)mu;
        g_rstd[b] = (float)(1.0 / sqrt(var + 1e-8));
    }
}

// ---------------- 8. column sums of Wxabs ----------------
__global__ void k_wcs(const float* __restrict__ W) {
    int k = threadIdx.x;
    float s = 0.f;
    for (int h = 0; h < HSZ; ++h) s += W[h * HSZ + k];
    g_wcs[k] = s;
}

// ---------------- 9. adp = LN(x1) @ Wxabs  (LN fused into epilogue) ----------
__global__ void k_adp(const float* __restrict__ W) {
    __shared__ float As[16][132];
    __shared__ float Bs[16][128];
    int b = blockIdx.z, n0 = blockIdx.x * 128;
    int tid = threadIdx.x, tx = tid & 15, ty = tid >> 4;
    float acc[8][8] = {};
    for (int k0 = 0; k0 < HSZ; k0 += 16) {
        for (int idx = tid; idx < 2048; idx += 256) {
            int r = idx >> 4, c = idx & 15;   // r = m row, c = k
            int n = n0 + r;
            As[c][r] = (n < NSZ) ? g_x1[(b * NSZ + n) * HSZ + k0 + c] : 0.f;
        }
        for (int idx = tid; idx < 2048; idx += 256) {
            int r = idx >> 7, c = idx & 127;
            Bs[r][c] = W[(k0 + r) * HSZ + c];
        }
        __syncthreads();
        #pragma unroll
        for (int kk = 0; kk < 16; ++kk) {
            float a[8], bv[8];
            *(float4*)&a[0]  = *(const float4*)&As[kk][ty * 8];
            *(float4*)&a[4]  = *(const float4*)&As[kk][ty * 8 + 4];
            *(float4*)&bv[0] = *(const float4*)&Bs[kk][tx * 8];
            *(float4*)&bv[4] = *(const float4*)&Bs[kk][tx * 8 + 4];
            #pragma unroll
            for (int i = 0; i < 8; ++i)
                #pragma unroll
                for (int j = 0; j < 8; ++j) acc[i][j] += a[i] * bv[j];
        }
        __syncthreads();
    }
    float mu = g_mu[b], rstd = g_rstd[b];
    #pragma unroll
    for (int i = 0; i < 8; ++i) {
        int n = n0 + ty * 8 + i;
        if (n >= NSZ) continue;
        #pragma unroll
        for (int j = 0; j < 8; ++j) {
            int k = tx * 8 + j;
            g_adp[(b * NSZ + n) * HSZ + k] = rstd * (acc[i][j] - mu * g_wcs[k]);
        }
    }
}

// ---------------- 10. adj = relu(adp @ x1^T)  (NT SGEMM, dominant) ----------
__global__ void k_adj() {
    __shared__ float As[16][132];
    __shared__ float Bs[16][132];
    int b  = blockIdx.z;
    int n0 = blockIdx.y * 128;
    int m0 = blockIdx.x * 128;
    int tid = threadIdx.x, tx = tid & 15, ty = tid >> 4;
    float acc[8][8] = {};
    for (int k0 = 0; k0 < HSZ; k0 += 16) {
        for (int idx = tid; idx < 2048; idx += 256) {
            int r = idx >> 4, c = idx & 15;
            int n = n0 + r;
            As[c][r] = (n < NSZ) ? g_adp[(b * NSZ + n) * HSZ + k0 + c] : 0.f;
        }
        for (int idx = tid; idx < 2048; idx += 256) {
            int r = idx >> 4, c = idx & 15;
            int m = m0 + r;
            Bs[c][r] = (m < NSZ) ? g_x1[(b * NSZ + m) * HSZ + k0 + c] : 0.f;
        }
        __syncthreads();
        #pragma unroll
        for (int kk = 0; kk < 16; ++kk) {
            float a[8], bv[8];
            *(float4*)&a[0]  = *(const float4*)&As[kk][ty * 8];
            *(float4*)&a[4]  = *(const float4*)&As[kk][ty * 8 + 4];
            *(float4*)&bv[0] = *(const float4*)&Bs[kk][tx * 8];
            *(float4*)&bv[4] = *(const float4*)&Bs[kk][tx * 8 + 4];
            #pragma unroll
            for (int i = 0; i < 8; ++i)
                #pragma unroll
                for (int j = 0; j < 8; ++j) acc[i][j] += a[i] * bv[j];
        }
        __syncthreads();
    }
    #pragma unroll
    for (int i = 0; i < 8; ++i) {
        int n = n0 + ty * 8 + i;
        if (n >= NSZ) continue;
        #pragma unroll
        for (int j = 0; j < 8; ++j) {
            int m = m0 + tx * 8 + j;
            if (m >= NSZ) continue;
            g_adj[(b * NSZ + n) * NSZ + m] = fmaxf(acc[i][j], 0.f);
        }
    }
}

// ---------------- 11. per-row top-20 + masked softmax ----------------
__global__ void k_topk(float* __restrict__ out) {
    __shared__ float vals[NSZ];
    __shared__ float rv[256];
    __shared__ int   ri[256];
    __shared__ float selv[KTOP];
    __shared__ int   seli[KTOP];
    __shared__ float svmax, sD;
    int n = blockIdx.x, b = blockIdx.y, tid = threadIdx.x;
    const float* row = &g_adj[(b * NSZ + n) * NSZ];
    for (int m = tid; m < NSZ; m += 256) vals[m] = row[m];
    __syncthreads();

    for (int it = 0; it < KTOP; ++it) {
        float bv = -1.f; int bi = NSZ;
        for (int m = tid; m < NSZ; m += 256) {
            float v = vals[m];
            if (v > bv) { bv = v; bi = m; }
        }
        rv[tid] = bv; ri[tid] = bi; __syncthreads();
        for (int st = 128; st > 0; st >>= 1) {
            if (tid < st) {
                float ov = rv[tid + st]; int oi = ri[tid + st];
                if (ov > rv[tid] || (ov == rv[tid] && oi < ri[tid])) { rv[tid] = ov; ri[tid] = oi; }
            }
            __syncthreads();
        }
        if (tid == 0) { selv[it] = rv[0]; seli[it] = ri[0]; vals[ri[0]] = -1.f; }
        __syncthreads();
    }

    if (tid == 0) {
        float vmax = selv[0];                       // row max (>= 0 after relu)
        float D = (float)(NSZ - KTOP) * expf(-vmax); // 1980 masked zeros: exp(0 - vmax)
        for (int it = 0; it < KTOP; ++it) D += expf(selv[it] - vmax);
        svmax = vmax; sD = D;
    }
    __syncthreads();

    float base = expf(-svmax) / sD;
    float* orow = &out[(b * NSZ + n) * NSZ];
    for (int m = tid; m < NSZ; m += 256) orow[m] = base;
    __syncthreads();
    if (tid < KTOP) orow[seli[tid]] = expf(selv[tid] - svmax) / sD;
}

// ---------------- launch ----------------
extern "C" void kernel_launch(void* const* d_in, const int* in_sizes, int n_in,
                              void* d_out, int out_size) {
    const float* x     = (const float*)d_in[0];
    const float* Ex    = (const float*)d_in[1];
    const float* nodes = (const float*)d_in[2];
    const float* Wd    = (const float*)d_in[3];
    const float* W     = (const float*)d_in[4];
    float* out = (float*)d_out;

    k_basis<<<(FLSZ * TSZ + 255) / 256, 256>>>();
    k_dft  <<<dim3(16, 5, BQ), 256>>>(x);
    k_invn <<<dim3(FLSZ, BQ), 256>>>();
    k_invf <<<dim3((NSZ + 255) / 256, BQ), 256>>>();
    k_xe   <<<dim3(16, 1, BQ), 256>>>(Ex);
    k_x1   <<<NSZ, 128>>>(nodes, Wd);
    k_ln   <<<BQ, 512>>>();
    k_wcs  <<<1, 128>>>(W);
    k_adp  <<<dim3(16, 1, BQ), 256>>>(W);
    k_adj  <<<dim3(16, 16, BQ), 256>>>();
    k_topk <<<dim3(NSZ, BQ), 256>>>(out);
}